// round 6
// baseline (speedup 1.0000x reference)
#include <cuda_runtime.h>
#include <cuda_fp16.h>
#include <cstdint>

// ---------------- problem constants (fixed by dataset) ----------------
#define M_TOTAL 4096      // B*S
#define K_DIM   768       // D
#define N_TOTAL 50257     // V

#define BM 256
#define BN 128
#define BK 64             // fp16: 64 elems = 128B row (SW128-style swizzle)
#define KC (K_DIM / BK)   // 12
#define STAGES 3
#define THREADS 256

#define A_BYTES (BM * 128)                  // 32768
#define B_BYTES (BN * 128)                  // 16384
#define STAGE_BYTES (A_BYTES + B_BYTES)     // 49152
#define SMEM_REQ (STAGES * STAGE_BYTES)     // 147456

// Scratch: fp16 activations and fp16 W_out (static device arrays = sanctioned path)
__device__ __align__(1024) __half g_h[M_TOTAL * K_DIM];
__device__ __align__(1024) __half g_bh[(size_t)N_TOTAL * K_DIM];

// ---------------- PTX helpers (baseline sm_80-class PTX only) ----------------
__device__ __forceinline__ uint32_t smem_u32(const void* p) {
    uint32_t a;
    asm("{ .reg .u64 t; cvta.to.shared.u64 t, %1; cvt.u32.u64 %0, t; }" : "=r"(a) : "l"(p));
    return a;
}
__device__ __forceinline__ void cp16(uint32_t sdst, const void* gsrc) {
    asm volatile("cp.async.cg.shared.global [%0], [%1], 16;" :: "r"(sdst), "l"(gsrc));
}
__device__ __forceinline__ void ldsm_x4(uint32_t* r, uint32_t addr) {
    asm volatile("ldmatrix.sync.aligned.m8n8.x4.shared.b16 {%0,%1,%2,%3}, [%4];"
                 : "=r"(r[0]), "=r"(r[1]), "=r"(r[2]), "=r"(r[3]) : "r"(addr));
}
__device__ __forceinline__ void mma16816(float* c, const uint32_t* a, uint32_t b0, uint32_t b1) {
    asm volatile(
        "mma.sync.aligned.m16n8k16.row.col.f32.f16.f16.f32 "
        "{%0,%1,%2,%3}, {%4,%5,%6,%7}, {%8,%9}, {%0,%1,%2,%3};"
        : "+f"(c[0]), "+f"(c[1]), "+f"(c[2]), "+f"(c[3])
        : "r"(a[0]), "r"(a[1]), "r"(a[2]), "r"(a[3]), "r"(b0), "r"(b1));
}

// -------- kernel 1: fused prep: rmsnorm (blocks < M) + W cvt (rest) --------
__global__ void prep_kernel(const int* __restrict__ tok,
                            const float* __restrict__ emb,
                            const float* __restrict__ w,
                            const float4* __restrict__ wout,
                            int M, int D, int n4, int cvtBlocks) {
    if (blockIdx.x < (unsigned)M) {
        int row = blockIdx.x;
        int t = tok[row];
        const float* e = emb + (size_t)t * D;

        float ss = 0.f;
        for (int i = threadIdx.x; i < D; i += blockDim.x) {
            float v = e[i];
            ss += v * v;
        }
        __shared__ float red[8];
        #pragma unroll
        for (int o = 16; o > 0; o >>= 1) ss += __shfl_xor_sync(~0u, ss, o);
        if ((threadIdx.x & 31) == 0) red[threadIdx.x >> 5] = ss;
        __syncthreads();
        if (threadIdx.x < 8) {
            float v = red[threadIdx.x];
            #pragma unroll
            for (int o = 4; o > 0; o >>= 1) v += __shfl_xor_sync(0xffu, v, o);
            if (threadIdx.x == 0) red[0] = v;
        }
        __syncthreads();
        float scale = rsqrtf(red[0] / (float)D + 1e-5f);

        __half* out = g_h + (size_t)row * D;
        for (int i = threadIdx.x; i < D; i += blockDim.x) {
            out[i] = __float2half_rn(e[i] * scale * w[i]);
        }
    } else {
        int i = (blockIdx.x - M) * blockDim.x + threadIdx.x;
        int stride = cvtBlocks * blockDim.x;
        uint2* dst = reinterpret_cast<uint2*>(g_bh);
        for (; i < n4; i += stride) {
            float4 v = wout[i];
            __half2 h0 = __floats2half2_rn(v.x, v.y);
            __half2 h1 = __floats2half2_rn(v.z, v.w);
            uint2 o;
            o.x = *reinterpret_cast<uint32_t*>(&h0);
            o.y = *reinterpret_cast<uint32_t*>(&h1);
            dst[i] = o;
        }
    }
}

// ---------------- kernel 2: fp16 mma.sync GEMM ----------------
// C[M,N] = g_h[M,K] * g_bh[N,K]^T
// BM=256, BN=128, BK=64, 3-stage cp.async, 8 warps: warp tile 64x64
// (fat warp tiles cut SMEM fragment traffic per FLOP: crossbar was the binding pipe)
__global__ void __launch_bounds__(THREADS, 1)
gemm_kernel(float* __restrict__ C) {
    extern __shared__ char smem[];
    const uint32_t sb = smem_u32(smem);

    const int tid  = threadIdx.x;
    const int lane = tid & 31;
    const int w    = tid >> 5;
    const int warp_m = w & 3;      // 4 warps over M: 64 rows each
    const int warp_n = w >> 2;     // 2 warps over N: 64 cols each
    const int g = lane >> 2;
    const int t = lane & 3;

    const int m0 = blockIdx.x * BM;     // m fast-varying -> B tiles L2-shared
    const int n0 = blockIdx.y * BN;

    const char* Ab = reinterpret_cast<const char*>(g_h);
    const char* Bb = reinterpret_cast<const char*>(g_bh);

    // ---- global->smem loaders ----
    const int rbase = tid >> 3;            // 0..31
    const int colb  = (tid & 7) * 16;      // byte col in 128B row

    auto load = [&](int kc, int s) {
        uint32_t abase = sb + (uint32_t)s * STAGE_BYTES;
        uint32_t bbase = abase + A_BYTES;
        #pragma unroll
        for (int p = 0; p < 8; p++) {
            int r = rbase + p * 32;
            uint32_t off = (uint32_t)(r * 128 + colb);
            cp16(abase + (off ^ ((off >> 3) & 0x70)),
                 Ab + (size_t)(m0 + r) * (K_DIM * 2) + kc * 128 + colb);
        }
        #pragma unroll
        for (int p = 0; p < 4; p++) {
            int r = rbase + p * 32;
            int rn = n0 + r; if (rn >= N_TOTAL) rn = N_TOTAL - 1;
            uint32_t off = (uint32_t)(r * 128 + colb);
            cp16(bbase + (off ^ ((off >> 3) & 0x70)),
                 Bb + (size_t)rn * (K_DIM * 2) + kc * 128 + colb);
        }
        asm volatile("cp.async.commit_group;");
    };

    // ---- ldmatrix address precompute (row offset + swizzle xor mask) ----
    const int lrow  = lane & 15;
    const int lkoff = (lane >> 4) << 4;    // 0 or 16 bytes
    uint32_t rowA[4], mskA[4];
    #pragma unroll
    for (int mt = 0; mt < 4; mt++) {
        uint32_t off = (uint32_t)((warp_m * 64 + mt * 16 + lrow) * 128 + lkoff);
        rowA[mt] = off;
        mskA[mt] = (off >> 3) & 0x70;
    }
    uint32_t rowB[4], mskB[4];
    #pragma unroll
    for (int np = 0; np < 4; np++) {
        uint32_t off = (uint32_t)((warp_n * 64 + np * 16 + lrow) * 128 + lkoff);
        rowB[np] = off;
        mskB[np] = (off >> 3) & 0x70;
    }

    float acc[4][8][4];   // 128 regs: warp tile 64x64
    #pragma unroll
    for (int mt = 0; mt < 4; mt++)
        #pragma unroll
        for (int nt = 0; nt < 8; nt++)
            #pragma unroll
            for (int i = 0; i < 4; i++) acc[mt][nt][i] = 0.f;

    auto compute = [&](int s) {
        const uint32_t abase = sb + (uint32_t)s * STAGE_BYTES;
        const uint32_t bbase = abase + A_BYTES;
        #pragma unroll
        for (int ks = 0; ks < 4; ks++) {
            const uint32_t kadd = (uint32_t)(ks * 32);
            uint32_t a[4][4];
            #pragma unroll
            for (int mt = 0; mt < 4; mt++)
                ldsm_x4(a[mt], abase + ((rowA[mt] + kadd) ^ mskA[mt]));
            #pragma unroll
            for (int np = 0; np < 4; np++) {
                uint32_t b[4];
                ldsm_x4(b, bbase + ((rowB[np] + kadd) ^ mskB[np]));
                #pragma unroll
                for (int mt = 0; mt < 4; mt++) {
                    mma16816(acc[mt][2 * np],     a[mt], b[0], b[2]);
                    mma16816(acc[mt][2 * np + 1], a[mt], b[1], b[3]);
                }
            }
        }
    };

    // ---- 3-stage pipeline ----
    load(0, 0);
    load(1, 1);
    for (int kc = 0; kc < KC; kc++) {
        if (kc < KC - 1) asm volatile("cp.async.wait_group 1;");
        else             asm volatile("cp.async.wait_group 0;");
        __syncthreads();
        if (kc + 2 < KC) load(kc + 2, (kc + 2) % STAGES);
        compute(kc % STAGES);
    }
    __syncthreads();   // protect smem reuse by epilogue

    // ---- epilogue: frags -> padded smem -> coalesced STG ----
    // per-warp buffer: 64 rows x 68 floats (272B row) = 17408B; 8 warps = 139264 <= SMEM_REQ
    const uint32_t buf = sb + (uint32_t)w * (64 * 272);
    #pragma unroll
    for (int mt = 0; mt < 4; mt++) {
        #pragma unroll
        for (int nt = 0; nt < 8; nt++) {
            uint32_t ad = buf + (uint32_t)((mt * 16 + g) * 272 + (nt * 8 + 2 * t) * 4);
            asm volatile("st.shared.v2.f32 [%0], {%1,%2};"
                         :: "r"(ad), "f"(acc[mt][nt][0]), "f"(acc[mt][nt][1]) : "memory");
            asm volatile("st.shared.v2.f32 [%0], {%1,%2};"
                         :: "r"(ad + 8 * 272), "f"(acc[mt][nt][2]), "f"(acc[mt][nt][3]) : "memory");
        }
    }
    __syncwarp();

    const int gcol0 = n0 + warp_n * 64;
    #pragma unroll 4
    for (int r = 0; r < 64; r++) {
        size_t rb = (size_t)(m0 + warp_m * 64 + r) * N_TOTAL;
        #pragma unroll
        for (int p = 0; p < 2; p++) {
            int cl = p * 32 + lane;
            int col = gcol0 + cl;
            float v;
            asm volatile("ld.shared.f32 %0, [%1];"
                         : "=f"(v) : "r"(buf + (uint32_t)(r * 272 + cl * 4)));
            if (col < N_TOTAL) C[rb + col] = v;
        }
    }
}

// ---------------------------------------------------------------------
extern "C" void kernel_launch(void* const* d_in, const int* in_sizes, int n_in,
                              void* d_out, int out_size) {
    const int*   tok  = (const int*)d_in[0];    // [M] int32 token ids
    const float* emb  = (const float*)d_in[1];  // [V,D]
    const float* wn   = (const float*)d_in[2];  // [D]
    const float* wout = (const float*)d_in[3];  // [V,D]
    float* out = (float*)d_out;

    int M = in_sizes[0];
    int D = in_sizes[2];
    int N = in_sizes[3] / D;

    // 1) fused: gather+RMSNorm->fp16  ||  W_out->fp16
    int n4 = (N * D) / 4;
    int cvtBlocks = 4096;
    prep_kernel<<<M + cvtBlocks, 256>>>(tok, emb, wn, (const float4*)wout,
                                        M, D, n4, cvtBlocks);

    // 2) fp16 mma.sync GEMM (m fast-varying: B tiles L2-shared)
    cudaFuncSetAttribute(gemm_kernel, cudaFuncAttributeMaxDynamicSharedMemorySize, SMEM_REQ);
    dim3 grid(M / BM, (N + BN - 1) / BN);
    gemm_kernel<<<grid, THREADS, SMEM_REQ>>>(out);
}

// round 7
// speedup vs baseline: 1.1321x; 1.1321x over previous
#include <cuda_runtime.h>
#include <cuda_fp16.h>
#include <cstdint>

// ---------------- problem constants (fixed by dataset) ----------------
#define M_TOTAL 4096      // B*S
#define K_DIM   768       // D
#define N_TOTAL 50257     // V

#define BM 128
#define BN 128
#define BK 64             // fp16: 64 elems = 128B row (SW128-style swizzle)
#define KC (K_DIM / BK)   // 12
#define STAGES 3
#define THREADS 128       // 4 warps: 2(m) x 2(n), warp tile 64x64

#define A_BYTES (BM * 128)                  // 16384
#define B_BYTES (BN * 128)                  // 16384
#define STAGE_BYTES (A_BYTES + B_BYTES)     // 32768
#define SMEM_REQ (STAGES * STAGE_BYTES)     // 98304 -> 2 CTAs/SM

// Scratch: fp16 activations and fp16 W_out (static device arrays = sanctioned path)
__device__ __align__(1024) __half g_h[M_TOTAL * K_DIM];
__device__ __align__(1024) __half g_bh[(size_t)N_TOTAL * K_DIM];

// ---------------- PTX helpers (baseline sm_80-class PTX only) ----------------
__device__ __forceinline__ uint32_t smem_u32(const void* p) {
    uint32_t a;
    asm("{ .reg .u64 t; cvta.to.shared.u64 t, %1; cvt.u32.u64 %0, t; }" : "=r"(a) : "l"(p));
    return a;
}
__device__ __forceinline__ void cp16(uint32_t sdst, const void* gsrc) {
    asm volatile("cp.async.cg.shared.global [%0], [%1], 16;" :: "r"(sdst), "l"(gsrc));
}
__device__ __forceinline__ void ldsm_x4(uint32_t* r, uint32_t addr) {
    asm volatile("ldmatrix.sync.aligned.m8n8.x4.shared.b16 {%0,%1,%2,%3}, [%4];"
                 : "=r"(r[0]), "=r"(r[1]), "=r"(r[2]), "=r"(r[3]) : "r"(addr));
}
__device__ __forceinline__ void mma16816(float* c, const uint32_t* a, uint32_t b0, uint32_t b1) {
    asm volatile(
        "mma.sync.aligned.m16n8k16.row.col.f32.f16.f16.f32 "
        "{%0,%1,%2,%3}, {%4,%5,%6,%7}, {%8,%9}, {%0,%1,%2,%3};"
        : "+f"(c[0]), "+f"(c[1]), "+f"(c[2]), "+f"(c[3])
        : "r"(a[0]), "r"(a[1]), "r"(a[2]), "r"(a[3]), "r"(b0), "r"(b1));
}

// -------- kernel 1: fused prep: rmsnorm (blocks < M) + W cvt (rest) --------
__global__ void prep_kernel(const int* __restrict__ tok,
                            const float* __restrict__ emb,
                            const float* __restrict__ w,
                            const float4* __restrict__ wout,
                            int M, int D, int n4, int cvtBlocks) {
    if (blockIdx.x < (unsigned)M) {
        int row = blockIdx.x;
        int t = tok[row];
        const float* e = emb + (size_t)t * D;

        float ss = 0.f;
        for (int i = threadIdx.x; i < D; i += blockDim.x) {
            float v = e[i];
            ss += v * v;
        }
        __shared__ float red[8];
        #pragma unroll
        for (int o = 16; o > 0; o >>= 1) ss += __shfl_xor_sync(~0u, ss, o);
        if ((threadIdx.x & 31) == 0) red[threadIdx.x >> 5] = ss;
        __syncthreads();
        if (threadIdx.x < 8) {
            float v = red[threadIdx.x];
            #pragma unroll
            for (int o = 4; o > 0; o >>= 1) v += __shfl_xor_sync(0xffu, v, o);
            if (threadIdx.x == 0) red[0] = v;
        }
        __syncthreads();
        float scale = rsqrtf(red[0] / (float)D + 1e-5f);

        __half* out = g_h + (size_t)row * D;
        for (int i = threadIdx.x; i < D; i += blockDim.x) {
            out[i] = __float2half_rn(e[i] * scale * w[i]);
        }
    } else {
        int i = (blockIdx.x - M) * blockDim.x + threadIdx.x;
        int stride = cvtBlocks * blockDim.x;
        uint2* dst = reinterpret_cast<uint2*>(g_bh);
        for (; i < n4; i += stride) {
            float4 v = wout[i];
            __half2 h0 = __floats2half2_rn(v.x, v.y);
            __half2 h1 = __floats2half2_rn(v.z, v.w);
            uint2 o;
            o.x = *reinterpret_cast<uint32_t*>(&h0);
            o.y = *reinterpret_cast<uint32_t*>(&h1);
            dst[i] = o;
        }
    }
}

// ---------------- kernel 2: fp16 mma.sync GEMM ----------------
// C[M,N] = g_h[M,K] * g_bh[N,K]^T
// CTA 128x128, 128 threads, 4 warps (2m x 2n), warp tile 64x64, 3-stage cp.async.
// 2 CTAs/SM: independent barriers keep the SM issuing while one CTA waits.
__global__ void __launch_bounds__(THREADS)
gemm_kernel(float* __restrict__ C) {
    extern __shared__ char smem[];
    const uint32_t sb = smem_u32(smem);

    const int tid  = threadIdx.x;
    const int lane = tid & 31;
    const int w    = tid >> 5;
    const int warp_m = w & 1;      // 2 warps over M: 64 rows each
    const int warp_n = w >> 1;     // 2 warps over N: 64 cols each
    const int g = lane >> 2;
    const int t = lane & 3;

    const int m0 = blockIdx.x * BM;     // m fast-varying -> B tiles L2-shared
    const int n0 = blockIdx.y * BN;

    const char* Ab = reinterpret_cast<const char*>(g_h);
    const char* Bb = reinterpret_cast<const char*>(g_bh);

    // ---- global->smem loaders (128 threads: 16 rows/pass) ----
    const int rbase = tid >> 3;            // 0..15
    const int colb  = (tid & 7) * 16;      // byte col in 128B row

    auto load = [&](int kc, int s) {
        uint32_t abase = sb + (uint32_t)s * STAGE_BYTES;
        uint32_t bbase = abase + A_BYTES;
        #pragma unroll
        for (int p = 0; p < 8; p++) {
            int r = rbase + p * 16;
            uint32_t off = (uint32_t)(r * 128 + colb);
            cp16(abase + (off ^ ((off >> 3) & 0x70)),
                 Ab + (size_t)(m0 + r) * (K_DIM * 2) + kc * 128 + colb);
        }
        #pragma unroll
        for (int p = 0; p < 8; p++) {
            int r = rbase + p * 16;
            int rn = n0 + r; if (rn >= N_TOTAL) rn = N_TOTAL - 1;
            uint32_t off = (uint32_t)(r * 128 + colb);
            cp16(bbase + (off ^ ((off >> 3) & 0x70)),
                 Bb + (size_t)rn * (K_DIM * 2) + kc * 128 + colb);
        }
        asm volatile("cp.async.commit_group;");
    };

    // ---- ldmatrix address precompute (row offset + swizzle xor mask) ----
    const int lrow  = lane & 15;
    const int lkoff = (lane >> 4) << 4;    // 0 or 16 bytes
    uint32_t rowA[4], mskA[4];
    #pragma unroll
    for (int mt = 0; mt < 4; mt++) {
        uint32_t off = (uint32_t)((warp_m * 64 + mt * 16 + lrow) * 128 + lkoff);
        rowA[mt] = off;
        mskA[mt] = (off >> 3) & 0x70;
    }
    uint32_t rowB[4], mskB[4];
    #pragma unroll
    for (int np = 0; np < 4; np++) {
        uint32_t off = (uint32_t)((warp_n * 64 + np * 16 + lrow) * 128 + lkoff);
        rowB[np] = off;
        mskB[np] = (off >> 3) & 0x70;
    }

    float acc[4][8][4];   // warp tile 64x64 = 128 acc regs
    #pragma unroll
    for (int mt = 0; mt < 4; mt++)
        #pragma unroll
        for (int nt = 0; nt < 8; nt++)
            #pragma unroll
            for (int i = 0; i < 4; i++) acc[mt][nt][i] = 0.f;

    // ks-level fragment double buffers (hide LDSM latency behind MMA issue)
    uint32_t afr[2][4][4];
    uint32_t bfr[2][4][4];

    auto ldfrags = [&](uint32_t abase, uint32_t bbase, int ks, int buf) {
        const uint32_t kadd = (uint32_t)(ks * 32);
        #pragma unroll
        for (int mt = 0; mt < 4; mt++)
            ldsm_x4(afr[buf][mt], abase + ((rowA[mt] + kadd) ^ mskA[mt]));
        #pragma unroll
        for (int np = 0; np < 4; np++)
            ldsm_x4(bfr[buf][np], bbase + ((rowB[np] + kadd) ^ mskB[np]));
    };

    auto mmas = [&](int buf) {
        #pragma unroll
        for (int np = 0; np < 4; np++) {
            #pragma unroll
            for (int mt = 0; mt < 4; mt++) {
                mma16816(acc[mt][2 * np],     afr[buf][mt], bfr[buf][np][0], bfr[buf][np][2]);
                mma16816(acc[mt][2 * np + 1], afr[buf][mt], bfr[buf][np][1], bfr[buf][np][3]);
            }
        }
    };

    // ---- 3-stage pipeline ----
    load(0, 0);
    load(1, 1);
    for (int kc = 0; kc < KC; kc++) {
        if (kc < KC - 1) asm volatile("cp.async.wait_group 1;");
        else             asm volatile("cp.async.wait_group 0;");
        __syncthreads();
        if (kc + 2 < KC) load(kc + 2, (kc + 2) % STAGES);

        const int s = kc % STAGES;
        const uint32_t abase = sb + (uint32_t)s * STAGE_BYTES;
        const uint32_t bbase = abase + A_BYTES;

        ldfrags(abase, bbase, 0, 0);
        #pragma unroll
        for (int ks = 0; ks < 4; ks++) {
            const int cur = ks & 1;
            if (ks < 3) ldfrags(abase, bbase, ks + 1, cur ^ 1);
            mmas(cur);
        }
    }
    __syncthreads();   // protect smem reuse by epilogue

    // ---- epilogue: frags -> padded smem -> coalesced STG ----
    // per-warp buffer: 64 rows x 68 floats (272B row) = 17408B; 4 warps = 69632 <= 98304
    const uint32_t buf = sb + (uint32_t)w * (64 * 272);
    #pragma unroll
    for (int mt = 0; mt < 4; mt++) {
        #pragma unroll
        for (int nt = 0; nt < 8; nt++) {
            uint32_t ad = buf + (uint32_t)((mt * 16 + g) * 272 + (nt * 8 + 2 * t) * 4);
            asm volatile("st.shared.v2.f32 [%0], {%1,%2};"
                         :: "r"(ad), "f"(acc[mt][nt][0]), "f"(acc[mt][nt][1]) : "memory");
            asm volatile("st.shared.v2.f32 [%0], {%1,%2};"
                         :: "r"(ad + 8 * 272), "f"(acc[mt][nt][2]), "f"(acc[mt][nt][3]) : "memory");
        }
    }
    __syncwarp();

    const int gcol0 = n0 + warp_n * 64;
    #pragma unroll 4
    for (int r = 0; r < 64; r++) {
        size_t rb = (size_t)(m0 + warp_m * 64 + r) * N_TOTAL;
        #pragma unroll
        for (int p = 0; p < 2; p++) {
            int cl = p * 32 + lane;
            int col = gcol0 + cl;
            float v;
            asm volatile("ld.shared.f32 %0, [%1];"
                         : "=f"(v) : "r"(buf + (uint32_t)(r * 272 + cl * 4)));
            if (col < N_TOTAL) C[rb + col] = v;
        }
    }
}

// ---------------------------------------------------------------------
extern "C" void kernel_launch(void* const* d_in, const int* in_sizes, int n_in,
                              void* d_out, int out_size) {
    const int*   tok  = (const int*)d_in[0];    // [M] int32 token ids
    const float* emb  = (const float*)d_in[1];  // [V,D]
    const float* wn   = (const float*)d_in[2];  // [D]
    const float* wout = (const float*)d_in[3];  // [V,D]
    float* out = (float*)d_out;

    int M = in_sizes[0];
    int D = in_sizes[2];
    int N = in_sizes[3] / D;

    // 1) fused: gather+RMSNorm->fp16  ||  W_out->fp16
    int n4 = (N * D) / 4;
    int cvtBlocks = 4096;
    prep_kernel<<<M + cvtBlocks, 256>>>(tok, emb, wn, (const float4*)wout,
                                        M, D, n4, cvtBlocks);

    // 2) fp16 mma.sync GEMM (m fast-varying: B tiles L2-shared)
    cudaFuncSetAttribute(gemm_kernel, cudaFuncAttributeMaxDynamicSharedMemorySize, SMEM_REQ);
    dim3 grid(M / BM, (N + BN - 1) / BN);
    gemm_kernel<<<grid, THREADS, SMEM_REQ>>>(out);
}